// round 11
// baseline (speedup 1.0000x reference)
#include <cuda_runtime.h>
#include <cuda_fp16.h>

// Problem constants (fixed by reference)
#define VOCAB      32000
#define EMBED_DIM  128
#define BATCH      32
#define MAX_TREES  512
#define NSEG       (BATCH * MAX_TREES)   // 16384

#define CONV_BLOCKS   4000               // blocks doing table conversion
#define BOUND_BLOCKS  65                 // blocks doing segment bounds

// Scratch (allocation-free __device__ globals)
__device__ int g_seg_start[NSEG + 1];
// Packed interleaved fp16 tables: per token, 512B record =
//   [128 fp16 key row | 128 fp16 value row] = 32 uint4 (lane l owns uint4 l).
// Row 0 (PAD token) is exactly zero -> safe padding target.
__device__ __align__(16) uint4 g_pack[VOCAB * 32];

// ---------------------------------------------------------------------------
// Kernel 0 (fused): blocks [0, CONV_BLOCKS) convert the f32 tables to the
// packed fp16 layout; remaining blocks binary-search segment boundaries.
// ---------------------------------------------------------------------------
__global__ void __launch_bounds__(256)
prep_kernel(const float4* __restrict__ C_hop,
            const float4* __restrict__ C_hop1,
            const int*    __restrict__ tree_ids, int n) {
    if (blockIdx.x < CONV_BLOCKS) {
        const int NT = VOCAB * 32;                 // 1,024,000 output uint4s
        int j = blockIdx.x * blockDim.x + threadIdx.x;
        if (j >= NT) return;
        const int r = j >> 5;                      // token row
        const int c = j & 31;                      // uint4 slot in 512B record
        const float4* src = (c < 16) ? C_hop : C_hop1;
        const int cc = c & 15;

        float4 a0 = __ldg(&src[r * 32 + 2 * cc]);
        float4 a1 = __ldg(&src[r * 32 + 2 * cc + 1]);

        union { __half2 h2[4]; uint4 u; } p;
        p.h2[0] = __floats2half2_rn(a0.x, a0.y);
        p.h2[1] = __floats2half2_rn(a0.z, a0.w);
        p.h2[2] = __floats2half2_rn(a1.x, a1.y);
        p.h2[3] = __floats2half2_rn(a1.z, a1.w);
        g_pack[j] = p.u;
    } else {
        int s = (blockIdx.x - CONV_BLOCKS) * blockDim.x + threadIdx.x;
        if (s > NSEG) return;
        int lo = 0, hi = n;
        while (lo < hi) {
            int mid = (lo + hi) >> 1;
            if (__ldg(&tree_ids[mid]) < s) lo = mid + 1;
            else hi = mid;
        }
        g_seg_start[s] = lo;
    }
}

// ---------------------------------------------------------------------------
// Helpers: packed f32x2 accumulate (Blackwell add.rn.f32x2) + fp16x8 adds
// ---------------------------------------------------------------------------
__device__ __forceinline__ void addf32x2(unsigned long long& a, float2 f) {
    unsigned long long b;
    asm("mov.b64 %0, {%1, %2};" : "=l"(b) : "f"(f.x), "f"(f.y));
    asm("add.rn.f32x2 %0, %0, %1;" : "+l"(a) : "l"(b));
}
__device__ __forceinline__ float2 u64_to_f2(unsigned long long a) {
    float2 f;
    asm("mov.b64 {%0, %1}, %2;" : "=f"(f.x), "=f"(f.y) : "l"(a));
    return f;
}
__device__ __forceinline__ uint4 hadd2x4(uint4 a, uint4 b) {
    union U { uint4 u; __half2 h[4]; };
    U x, y, r; x.u = a; y.u = b;
    r.h[0] = __hadd2(x.h[0], y.h[0]);
    r.h[1] = __hadd2(x.h[1], y.h[1]);
    r.h[2] = __hadd2(x.h[2], y.h[2]);
    r.h[3] = __hadd2(x.h[3], y.h[3]);
    return r.u;
}
__device__ __forceinline__ void flush_set(unsigned long long acc[4], uint4 s) {
    union { uint4 u; __half2 h[4]; } c; c.u = s;
    addf32x2(acc[0], __half22float2(c.h[0]));
    addf32x2(acc[1], __half22float2(c.h[1]));
    addf32x2(acc[2], __half22float2(c.h[2]));
    addf32x2(acc[3], __half22float2(c.h[3]));
}

// ---------------------------------------------------------------------------
// Kernel 2: ONE warp per segment, minimal register footprint for occupancy.
// One 512B warp load per token fetches BOTH tables (lanes 0-15 key row,
// lanes 16-31 value row). Two rotating fp16 HADD2 sets, flushed into packed
// f32x2 accumulators every 16 tokens (each set sums <=8 tokens, bounding
// fp16 rounding). 4 loads in flight per lane.
// ---------------------------------------------------------------------------
__global__ void __launch_bounds__(256, 6)
seg_sum_kernel(const int* __restrict__ token_ids,
               float4*    __restrict__ out)        // [2][NSEG][32] float4
{
    const int seg  = (blockIdx.x * blockDim.x + threadIdx.x) >> 5;
    const int lane = threadIdx.x & 31;
    if (seg >= NSEG) return;

    const int beg = g_seg_start[seg];
    const int end = g_seg_start[seg + 1];

    unsigned long long acc[4] = {0ull, 0ull, 0ull, 0ull};
    const uint4 z4 = make_uint4(0u, 0u, 0u, 0u);

    int base = beg;
    // Full 32-token chunks
    for (; base + 32 <= end; base += 32) {
        const int myid = __ldg(&token_ids[base + lane]);
        #pragma unroll
        for (int half = 0; half < 2; half++) {
            uint4 h0 = z4, h1 = z4;
            #pragma unroll
            for (int u = 0; u < 16; u += 4) {
                const int q = half * 16 + u;
                int t0 = __shfl_sync(0xffffffffu, myid, q + 0);
                int t1 = __shfl_sync(0xffffffffu, myid, q + 1);
                int t2 = __shfl_sync(0xffffffffu, myid, q + 2);
                int t3 = __shfl_sync(0xffffffffu, myid, q + 3);
                uint4 r0 = __ldcg(&g_pack[t0 * 32 + lane]);
                uint4 r1 = __ldcg(&g_pack[t1 * 32 + lane]);
                uint4 r2 = __ldcg(&g_pack[t2 * 32 + lane]);
                uint4 r3 = __ldcg(&g_pack[t3 * 32 + lane]);
                h0 = hadd2x4(h0, r0);
                h1 = hadd2x4(h1, r1);
                h0 = hadd2x4(h0, r2);
                h1 = hadd2x4(h1, r3);
            }
            flush_set(acc, h0);
            flush_set(acc, h1);
        }
    }
    // Remainder (< 32 tokens): pad to multiple of 4 with token 0 (zero row).
    if (base < end) {
        const int valid = end - base;                 // 1..31
        const int myid  = (lane < valid) ? __ldg(&token_ids[base + lane]) : 0;
        const int lim   = (valid + 3) & ~3;
        uint4 h0 = z4, h1 = z4;
        for (int u = 0; u < lim; u += 4) {
            int t0 = __shfl_sync(0xffffffffu, myid, u + 0);
            int t1 = __shfl_sync(0xffffffffu, myid, u + 1);
            int t2 = __shfl_sync(0xffffffffu, myid, u + 2);
            int t3 = __shfl_sync(0xffffffffu, myid, u + 3);
            uint4 r0 = __ldcg(&g_pack[t0 * 32 + lane]);
            uint4 r1 = __ldcg(&g_pack[t1 * 32 + lane]);
            uint4 r2 = __ldcg(&g_pack[t2 * 32 + lane]);
            uint4 r3 = __ldcg(&g_pack[t3 * 32 + lane]);
            h0 = hadd2x4(h0, r0);
            h1 = hadd2x4(h1, r1);
            h0 = hadd2x4(h0, r2);
            h1 = hadd2x4(h1, r3);
            if ((u & 12) == 12) {                     // flush every 16 tokens
                flush_set(acc, h0); flush_set(acc, h1);
                h0 = z4; h1 = z4;
            }
        }
        flush_set(acc, h0);
        flush_set(acc, h1);
    }

    float2 f0 = u64_to_f2(acc[0]);
    float2 f1 = u64_to_f2(acc[1]);
    float2 f2 = u64_to_f2(acc[2]);
    float2 f3 = u64_to_f2(acc[3]);

    // lanes 0-15: key row floats [8*lane, 8*lane+8); lanes 16-31: value row.
    const int tbl = lane >> 4;
    const int col = lane & 15;
    float4* dst = &out[(((size_t)tbl * NSEG) + seg) * 32 + col * 2];
    dst[0] = make_float4(f0.x, f0.y, f1.x, f1.y);
    dst[1] = make_float4(f2.x, f2.y, f3.x, f3.y);
}

// ---------------------------------------------------------------------------
// Launch
// ---------------------------------------------------------------------------
extern "C" void kernel_launch(void* const* d_in, const int* in_sizes, int n_in,
                              void* d_out, int out_size) {
    const int*    token_ids = (const int*)   d_in[0];
    const int*    tree_ids  = (const int*)   d_in[1];
    const float4* C_hop     = (const float4*)d_in[2];
    const float4* C_hop1    = (const float4*)d_in[3];
    float4*       out       = (float4*)      d_out;

    const int n = in_sizes[0];  // TOTAL_TOKENS

    // Kernel 0: fused table conversion + segment bounds
    prep_kernel<<<CONV_BLOCKS + BOUND_BLOCKS, 256>>>(C_hop, C_hop1, tree_ids, n);

    // Kernel 2: 1 warp/segment -> 16384 warps = 2048 blocks
    seg_sum_kernel<<<NSEG * 32 / 256, 256>>>(token_ids, out);
}

// round 12
// speedup vs baseline: 1.0171x; 1.0171x over previous
#include <cuda_runtime.h>
#include <cuda_fp16.h>

// Problem constants (fixed by reference)
#define VOCAB      32000
#define EMBED_DIM  128
#define BATCH      32
#define MAX_TREES  512
#define NSEG       (BATCH * MAX_TREES)   // 16384

#define CONV_BLOCKS   2000               // blocks doing table conversion (2 slots/thread)
#define BOUND_BLOCKS  65                 // blocks doing segment bounds

// Scratch (allocation-free __device__ globals)
__device__ int g_seg_start[NSEG + 1];
// Packed interleaved fp16 tables: per token, 512B record =
//   [128 fp16 key row | 128 fp16 value row] = 32 uint4 (lane l owns uint4 l).
// Row 0 (PAD token) is exactly zero -> safe padding target.
__device__ __align__(16) uint4 g_pack[VOCAB * 32];

// ---------------------------------------------------------------------------
// Kernel 0 (fused): blocks [0, CONV_BLOCKS) convert the f32 tables to packed
// fp16 (2 output uint4 per thread -> 4 loads in flight, latency-bound fix);
// remaining blocks binary-search segment boundaries.
// ---------------------------------------------------------------------------
__global__ void __launch_bounds__(256)
prep_kernel(const float4* __restrict__ C_hop,
            const float4* __restrict__ C_hop1,
            const int*    __restrict__ tree_ids, int n) {
    if (blockIdx.x < CONV_BLOCKS) {
        const int NT = VOCAB * 32;                 // 1,024,000 output uint4s
        int j0 = (blockIdx.x * blockDim.x + threadIdx.x) * 2;
        #pragma unroll
        for (int k = 0; k < 2; k++) {
            int j = j0 + k;
            if (j >= NT) break;
            const int r = j >> 5;                  // token row
            const int c = j & 31;                  // uint4 slot in 512B record
            const float4* src = (c < 16) ? C_hop : C_hop1;
            const int cc = c & 15;

            float4 a0 = __ldg(&src[r * 32 + 2 * cc]);
            float4 a1 = __ldg(&src[r * 32 + 2 * cc + 1]);

            union { __half2 h2[4]; uint4 u; } p;
            p.h2[0] = __floats2half2_rn(a0.x, a0.y);
            p.h2[1] = __floats2half2_rn(a0.z, a0.w);
            p.h2[2] = __floats2half2_rn(a1.x, a1.y);
            p.h2[3] = __floats2half2_rn(a1.z, a1.w);
            g_pack[j] = p.u;
        }
    } else {
        int s = (blockIdx.x - CONV_BLOCKS) * blockDim.x + threadIdx.x;
        if (s > NSEG) return;
        int lo = 0, hi = n;
        while (lo < hi) {
            int mid = (lo + hi) >> 1;
            if (__ldg(&tree_ids[mid]) < s) lo = mid + 1;
            else hi = mid;
        }
        g_seg_start[s] = lo;
    }
}

// ---------------------------------------------------------------------------
// Helpers: packed f32x2 accumulate (Blackwell add.rn.f32x2) + fp16x8 adds
// ---------------------------------------------------------------------------
__device__ __forceinline__ void addf32x2(unsigned long long& a, float2 f) {
    unsigned long long b;
    asm("mov.b64 %0, {%1, %2};" : "=l"(b) : "f"(f.x), "f"(f.y));
    asm("add.rn.f32x2 %0, %0, %1;" : "+l"(a) : "l"(b));
}
__device__ __forceinline__ float2 u64_to_f2(unsigned long long a) {
    float2 f;
    asm("mov.b64 {%0, %1}, %2;" : "=f"(f.x), "=f"(f.y) : "l"(a));
    return f;
}
__device__ __forceinline__ uint4 hadd2x4(uint4 a, uint4 b) {
    union U { uint4 u; __half2 h[4]; };
    U x, y, r; x.u = a; y.u = b;
    r.h[0] = __hadd2(x.h[0], y.h[0]);
    r.h[1] = __hadd2(x.h[1], y.h[1]);
    r.h[2] = __hadd2(x.h[2], y.h[2]);
    r.h[3] = __hadd2(x.h[3], y.h[3]);
    return r.u;
}
__device__ __forceinline__ void flush_set(unsigned long long acc[4], uint4 s) {
    union { uint4 u; __half2 h[4]; } c; c.u = s;
    addf32x2(acc[0], __half22float2(c.h[0]));
    addf32x2(acc[1], __half22float2(c.h[1]));
    addf32x2(acc[2], __half22float2(c.h[2]));
    addf32x2(acc[3], __half22float2(c.h[3]));
}

// ---------------------------------------------------------------------------
// Kernel 2: ONE warp per segment. One 512B warp load per token fetches BOTH
// tables (lanes 0-15 key row, 16-31 value row). EIGHT loads issued back-to-
// back per group (the config that sustained 18.8 TB/s in f32), consumed by
// cheap HADD2 into 2 rotating fp16 sets; flushed to packed f32x2 every 16
// tokens (each set sums <=8 tokens -> bounded fp16 rounding).
// ---------------------------------------------------------------------------
__global__ void __launch_bounds__(256)
seg_sum_kernel(const int* __restrict__ token_ids,
               float4*    __restrict__ out)        // [2][NSEG][32] float4
{
    const int seg  = (blockIdx.x * blockDim.x + threadIdx.x) >> 5;
    const int lane = threadIdx.x & 31;
    if (seg >= NSEG) return;

    const int beg = g_seg_start[seg];
    const int end = g_seg_start[seg + 1];

    unsigned long long acc[4] = {0ull, 0ull, 0ull, 0ull};
    const uint4 z4 = make_uint4(0u, 0u, 0u, 0u);

    int base = beg;
    // Full 32-token chunks
    for (; base + 32 <= end; base += 32) {
        const int myid = __ldg(&token_ids[base + lane]);
        #pragma unroll
        for (int half = 0; half < 2; half++) {
            uint4 h0 = z4, h1 = z4;
            #pragma unroll
            for (int g = 0; g < 2; g++) {
                const int q = half * 16 + g * 8;
                int t0 = __shfl_sync(0xffffffffu, myid, q + 0);
                int t1 = __shfl_sync(0xffffffffu, myid, q + 1);
                int t2 = __shfl_sync(0xffffffffu, myid, q + 2);
                int t3 = __shfl_sync(0xffffffffu, myid, q + 3);
                int t4 = __shfl_sync(0xffffffffu, myid, q + 4);
                int t5 = __shfl_sync(0xffffffffu, myid, q + 5);
                int t6 = __shfl_sync(0xffffffffu, myid, q + 6);
                int t7 = __shfl_sync(0xffffffffu, myid, q + 7);
                uint4 r0 = __ldcg(&g_pack[t0 * 32 + lane]);
                uint4 r1 = __ldcg(&g_pack[t1 * 32 + lane]);
                uint4 r2 = __ldcg(&g_pack[t2 * 32 + lane]);
                uint4 r3 = __ldcg(&g_pack[t3 * 32 + lane]);
                uint4 r4 = __ldcg(&g_pack[t4 * 32 + lane]);
                uint4 r5 = __ldcg(&g_pack[t5 * 32 + lane]);
                uint4 r6 = __ldcg(&g_pack[t6 * 32 + lane]);
                uint4 r7 = __ldcg(&g_pack[t7 * 32 + lane]);
                h0 = hadd2x4(h0, r0);
                h1 = hadd2x4(h1, r1);
                h0 = hadd2x4(h0, r2);
                h1 = hadd2x4(h1, r3);
                h0 = hadd2x4(h0, r4);
                h1 = hadd2x4(h1, r5);
                h0 = hadd2x4(h0, r6);
                h1 = hadd2x4(h1, r7);
            }
            flush_set(acc, h0);
            flush_set(acc, h1);
        }
    }
    // Remainder (< 32 tokens): pad to multiple of 4 with token 0 (zero row).
    if (base < end) {
        const int valid = end - base;                 // 1..31
        const int myid  = (lane < valid) ? __ldg(&token_ids[base + lane]) : 0;
        const int lim   = (valid + 3) & ~3;
        uint4 h0 = z4, h1 = z4;
        for (int u = 0; u < lim; u += 4) {
            int t0 = __shfl_sync(0xffffffffu, myid, u + 0);
            int t1 = __shfl_sync(0xffffffffu, myid, u + 1);
            int t2 = __shfl_sync(0xffffffffu, myid, u + 2);
            int t3 = __shfl_sync(0xffffffffu, myid, u + 3);
            uint4 r0 = __ldcg(&g_pack[t0 * 32 + lane]);
            uint4 r1 = __ldcg(&g_pack[t1 * 32 + lane]);
            uint4 r2 = __ldcg(&g_pack[t2 * 32 + lane]);
            uint4 r3 = __ldcg(&g_pack[t3 * 32 + lane]);
            h0 = hadd2x4(h0, r0);
            h1 = hadd2x4(h1, r1);
            h0 = hadd2x4(h0, r2);
            h1 = hadd2x4(h1, r3);
            if ((u & 12) == 12) {                     // flush every 16 tokens
                flush_set(acc, h0); flush_set(acc, h1);
                h0 = z4; h1 = z4;
            }
        }
        flush_set(acc, h0);
        flush_set(acc, h1);
    }

    float2 f0 = u64_to_f2(acc[0]);
    float2 f1 = u64_to_f2(acc[1]);
    float2 f2 = u64_to_f2(acc[2]);
    float2 f3 = u64_to_f2(acc[3]);

    // lanes 0-15: key row floats [8*lane, 8*lane+8); lanes 16-31: value row.
    const int tbl = lane >> 4;
    const int col = lane & 15;
    float4* dst = &out[(((size_t)tbl * NSEG) + seg) * 32 + col * 2];
    dst[0] = make_float4(f0.x, f0.y, f1.x, f1.y);
    dst[1] = make_float4(f2.x, f2.y, f3.x, f3.y);
}

// ---------------------------------------------------------------------------
// Launch
// ---------------------------------------------------------------------------
extern "C" void kernel_launch(void* const* d_in, const int* in_sizes, int n_in,
                              void* d_out, int out_size) {
    const int*    token_ids = (const int*)   d_in[0];
    const int*    tree_ids  = (const int*)   d_in[1];
    const float4* C_hop     = (const float4*)d_in[2];
    const float4* C_hop1    = (const float4*)d_in[3];
    float4*       out       = (float4*)      d_out;

    const int n = in_sizes[0];  // TOTAL_TOKENS

    // Kernel 0: fused table conversion + segment bounds
    prep_kernel<<<CONV_BLOCKS + BOUND_BLOCKS, 256>>>(C_hop, C_hop1, tree_ids, n);

    // Kernel 2: 1 warp/segment -> 16384 warps = 2048 blocks
    seg_sum_kernel<<<NSEG * 32 / 256, 256>>>(token_ids, out);
}

// round 13
// speedup vs baseline: 1.0297x; 1.0125x over previous
#include <cuda_runtime.h>
#include <cuda_fp16.h>

// Problem constants (fixed by reference)
#define VOCAB      32000
#define EMBED_DIM  128
#define BATCH      32
#define MAX_TREES  512
#define NSEG       (BATCH * MAX_TREES)   // 16384

#define CONV_BLOCKS   4000               // blocks doing table conversion
#define BOUND_BLOCKS  65                 // blocks doing segment bounds

// Scratch (allocation-free __device__ globals)
__device__ int g_seg_start[NSEG + 1];
// Packed interleaved fp16 tables: per token, 512B record =
//   [128 fp16 key row | 128 fp16 value row] = 32 uint4 (lane l owns uint4 l).
// Row 0 (PAD token) is exactly zero -> safe padding target.
__device__ __align__(16) uint4 g_pack[VOCAB * 32];

// ---------------------------------------------------------------------------
// Kernel 0 (fused): blocks [0, CONV_BLOCKS) convert the f32 tables to packed
// fp16 (1 output uint4/thread — the empirically fastest prep form);
// remaining blocks binary-search segment boundaries.
// ---------------------------------------------------------------------------
__global__ void __launch_bounds__(256)
prep_kernel(const float4* __restrict__ C_hop,
            const float4* __restrict__ C_hop1,
            const int*    __restrict__ tree_ids, int n) {
    if (blockIdx.x < CONV_BLOCKS) {
        const int NT = VOCAB * 32;                 // 1,024,000 output uint4s
        int j = blockIdx.x * blockDim.x + threadIdx.x;
        if (j >= NT) return;
        const int r = j >> 5;                      // token row
        const int c = j & 31;                      // uint4 slot in 512B record
        const float4* src = (c < 16) ? C_hop : C_hop1;
        const int cc = c & 15;

        float4 a0 = __ldg(&src[r * 32 + 2 * cc]);
        float4 a1 = __ldg(&src[r * 32 + 2 * cc + 1]);

        union { __half2 h2[4]; uint4 u; } p;
        p.h2[0] = __floats2half2_rn(a0.x, a0.y);
        p.h2[1] = __floats2half2_rn(a0.z, a0.w);
        p.h2[2] = __floats2half2_rn(a1.x, a1.y);
        p.h2[3] = __floats2half2_rn(a1.z, a1.w);
        g_pack[j] = p.u;
    } else {
        int s = (blockIdx.x - CONV_BLOCKS) * blockDim.x + threadIdx.x;
        if (s > NSEG) return;
        int lo = 0, hi = n;
        while (lo < hi) {
            int mid = (lo + hi) >> 1;
            if (__ldg(&tree_ids[mid]) < s) lo = mid + 1;
            else hi = mid;
        }
        g_seg_start[s] = lo;
    }
}

// ---------------------------------------------------------------------------
// Helpers: packed f32x2 accumulate (Blackwell add.rn.f32x2) + fp16x8 adds
// ---------------------------------------------------------------------------
__device__ __forceinline__ void addf32x2(unsigned long long& a, float2 f) {
    unsigned long long b;
    asm("mov.b64 %0, {%1, %2};" : "=l"(b) : "f"(f.x), "f"(f.y));
    asm("add.rn.f32x2 %0, %0, %1;" : "+l"(a) : "l"(b));
}
__device__ __forceinline__ float2 u64_to_f2(unsigned long long a) {
    float2 f;
    asm("mov.b64 {%0, %1}, %2;" : "=f"(f.x), "=f"(f.y) : "l"(a));
    return f;
}
__device__ __forceinline__ uint4 hadd2x4(uint4 a, uint4 b) {
    union U { uint4 u; __half2 h[4]; };
    U x, y, r; x.u = a; y.u = b;
    r.h[0] = __hadd2(x.h[0], y.h[0]);
    r.h[1] = __hadd2(x.h[1], y.h[1]);
    r.h[2] = __hadd2(x.h[2], y.h[2]);
    r.h[3] = __hadd2(x.h[3], y.h[3]);
    return r.u;
}
__device__ __forceinline__ void flush_set(unsigned long long acc[4], uint4 s) {
    union { uint4 u; __half2 h[4]; } c; c.u = s;
    addf32x2(acc[0], __half22float2(c.h[0]));
    addf32x2(acc[1], __half22float2(c.h[1]));
    addf32x2(acc[2], __half22float2(c.h[2]));
    addf32x2(acc[3], __half22float2(c.h[3]));
}

// ---------------------------------------------------------------------------
// Kernel 2: TWO warps per segment (chunk-split halves), 4 segments per
// 256-thread block, 4KB smem combine. One 512B warp load per token fetches
// BOTH tables (lanes 0-15 key row, 16-31 value row). Lean 4-deep load loop
// + HADD2 into 2 rotating fp16 sets (flushed to packed f32x2 every 16
// tokens -> each set sums <=8 tokens). Pinned to 6 blocks/SM for occupancy.
// ---------------------------------------------------------------------------
__global__ void __launch_bounds__(256, 6)
seg_sum_kernel(const int* __restrict__ token_ids,
               float4*    __restrict__ out)        // [2][NSEG][32] float4
{
    __shared__ unsigned long long part[4][32][4];  // 4KB

    const int tid   = threadIdx.x;
    const int w     = tid >> 5;          // warp 0..7
    const int lane  = tid & 31;
    const int which = w >> 1;            // segment slot 0..3
    const int sub   = w & 1;             // half 0/1

    const int seg = blockIdx.x * 4 + which;        // grid = NSEG/4
    const int beg = g_seg_start[seg];
    const int end = g_seg_start[seg + 1];
    const int cnt = end - beg;

    const int T     = (cnt + 31) >> 5;   // total 32-token chunks
    const int split = T >> 1;            // warp0: [0,split), warp1: [split,T)
    const int cbeg  = sub ? split : 0;
    const int cend  = sub ? T     : split;

    unsigned long long acc[4] = {0ull, 0ull, 0ull, 0ull};
    const uint4 z4 = make_uint4(0u, 0u, 0u, 0u);

    for (int c = cbeg; c < cend; c++) {
        const int base  = beg + (c << 5);
        const int valid = min(32, end - base);      // 32 except (maybe) last
        const int myid  = (lane < valid) ? __ldg(&token_ids[base + lane]) : 0;
        const int lim   = (valid + 3) & ~3;         // pad to mult of 4 (tok 0)

        uint4 h0 = z4, h1 = z4;
        for (int u = 0; u < lim; u += 4) {
            int t0 = __shfl_sync(0xffffffffu, myid, u + 0);
            int t1 = __shfl_sync(0xffffffffu, myid, u + 1);
            int t2 = __shfl_sync(0xffffffffu, myid, u + 2);
            int t3 = __shfl_sync(0xffffffffu, myid, u + 3);
            uint4 r0 = __ldcg(&g_pack[t0 * 32 + lane]);
            uint4 r1 = __ldcg(&g_pack[t1 * 32 + lane]);
            uint4 r2 = __ldcg(&g_pack[t2 * 32 + lane]);
            uint4 r3 = __ldcg(&g_pack[t3 * 32 + lane]);
            h0 = hadd2x4(h0, r0);
            h1 = hadd2x4(h1, r1);
            h0 = hadd2x4(h0, r2);
            h1 = hadd2x4(h1, r3);
            if ((u & 12) == 12) {                   // flush every 16 tokens
                flush_set(acc, h0); flush_set(acc, h1);
                h0 = z4; h1 = z4;
            }
        }
        flush_set(acc, h0);
        flush_set(acc, h1);
    }

    // Combine the two warps of each segment via smem.
    if (sub == 1) {
        part[which][lane][0] = acc[0];
        part[which][lane][1] = acc[1];
        part[which][lane][2] = acc[2];
        part[which][lane][3] = acc[3];
    }
    __syncthreads();

    if (sub == 0) {
        float2 f0 = u64_to_f2(acc[0]), g0 = u64_to_f2(part[which][lane][0]);
        float2 f1 = u64_to_f2(acc[1]), g1 = u64_to_f2(part[which][lane][1]);
        float2 f2 = u64_to_f2(acc[2]), g2 = u64_to_f2(part[which][lane][2]);
        float2 f3 = u64_to_f2(acc[3]), g3 = u64_to_f2(part[which][lane][3]);

        // lanes 0-15: key row floats [8*lane, 8*lane+8); lanes 16-31: value.
        const int tbl = lane >> 4;
        const int col = lane & 15;
        float4* dst = &out[(((size_t)tbl * NSEG) + seg) * 32 + col * 2];
        dst[0] = make_float4(f0.x + g0.x, f0.y + g0.y, f1.x + g1.x, f1.y + g1.y);
        dst[1] = make_float4(f2.x + g2.x, f2.y + g2.y, f3.x + g3.x, f3.y + g3.y);
    }
}

// ---------------------------------------------------------------------------
// Launch
// ---------------------------------------------------------------------------
extern "C" void kernel_launch(void* const* d_in, const int* in_sizes, int n_in,
                              void* d_out, int out_size) {
    const int*    token_ids = (const int*)   d_in[0];
    const int*    tree_ids  = (const int*)   d_in[1];
    const float4* C_hop     = (const float4*)d_in[2];
    const float4* C_hop1    = (const float4*)d_in[3];
    float4*       out       = (float4*)      d_out;

    const int n = in_sizes[0];  // TOTAL_TOKENS

    // Kernel 0: fused table conversion + segment bounds
    prep_kernel<<<CONV_BLOCKS + BOUND_BLOCKS, 256>>>(C_hop, C_hop1, tree_ids, n);

    // Kernel 2: 2 warps/segment, 4 segments/block -> 4096 blocks
    seg_sum_kernel<<<NSEG / 4, 256>>>(token_ids, out);
}

// round 14
// speedup vs baseline: 1.0902x; 1.0587x over previous
#include <cuda_runtime.h>
#include <cuda_fp16.h>
#include <cuda_pipeline.h>

// Problem constants (fixed by reference)
#define VOCAB      32000
#define EMBED_DIM  128
#define BATCH      32
#define MAX_TREES  512
#define NSEG       (BATCH * MAX_TREES)   // 16384

#define CONV_BLOCKS   4000               // blocks doing table conversion
#define BOUND_BLOCKS  65                 // blocks doing segment bounds

// Scratch (allocation-free __device__ globals)
__device__ int g_seg_start[NSEG + 1];
// Packed interleaved fp16 tables: per token, 512B record =
//   [128 fp16 key row | 128 fp16 value row] = 32 uint4 (lane l owns uint4 l).
// Row 0 (PAD token) is exactly zero -> safe padding target.
__device__ __align__(16) uint4 g_pack[VOCAB * 32];

// ---------------------------------------------------------------------------
// Kernel 0 (fused): blocks [0, CONV_BLOCKS) convert the f32 tables to packed
// fp16; remaining blocks binary-search segment boundaries.
// ---------------------------------------------------------------------------
__global__ void __launch_bounds__(256)
prep_kernel(const float4* __restrict__ C_hop,
            const float4* __restrict__ C_hop1,
            const int*    __restrict__ tree_ids, int n) {
    if (blockIdx.x < CONV_BLOCKS) {
        const int NT = VOCAB * 32;                 // 1,024,000 output uint4s
        int j = blockIdx.x * blockDim.x + threadIdx.x;
        if (j >= NT) return;
        const int r = j >> 5;                      // token row
        const int c = j & 31;                      // uint4 slot in 512B record
        const float4* src = (c < 16) ? C_hop : C_hop1;
        const int cc = c & 15;

        float4 a0 = __ldg(&src[r * 32 + 2 * cc]);
        float4 a1 = __ldg(&src[r * 32 + 2 * cc + 1]);

        union { __half2 h2[4]; uint4 u; } p;
        p.h2[0] = __floats2half2_rn(a0.x, a0.y);
        p.h2[1] = __floats2half2_rn(a0.z, a0.w);
        p.h2[2] = __floats2half2_rn(a1.x, a1.y);
        p.h2[3] = __floats2half2_rn(a1.z, a1.w);
        g_pack[j] = p.u;
    } else {
        int s = (blockIdx.x - CONV_BLOCKS) * blockDim.x + threadIdx.x;
        if (s > NSEG) return;
        int lo = 0, hi = n;
        while (lo < hi) {
            int mid = (lo + hi) >> 1;
            if (__ldg(&tree_ids[mid]) < s) lo = mid + 1;
            else hi = mid;
        }
        g_seg_start[s] = lo;
    }
}

// ---------------------------------------------------------------------------
// Helpers: packed f32x2 accumulate (Blackwell add.rn.f32x2) + fp16x8 adds
// ---------------------------------------------------------------------------
__device__ __forceinline__ void addf32x2(unsigned long long& a, float2 f) {
    unsigned long long b;
    asm("mov.b64 %0, {%1, %2};" : "=l"(b) : "f"(f.x), "f"(f.y));
    asm("add.rn.f32x2 %0, %0, %1;" : "+l"(a) : "l"(b));
}
__device__ __forceinline__ float2 u64_to_f2(unsigned long long a) {
    float2 f;
    asm("mov.b64 {%0, %1}, %2;" : "=f"(f.x), "=f"(f.y) : "l"(a));
    return f;
}
__device__ __forceinline__ uint4 hadd2x4(uint4 a, uint4 b) {
    union U { uint4 u; __half2 h[4]; };
    U x, y, r; x.u = a; y.u = b;
    r.h[0] = __hadd2(x.h[0], y.h[0]);
    r.h[1] = __hadd2(x.h[1], y.h[1]);
    r.h[2] = __hadd2(x.h[2], y.h[2]);
    r.h[3] = __hadd2(x.h[3], y.h[3]);
    return r.u;
}
__device__ __forceinline__ void flush_set(unsigned long long acc[4], uint4 s) {
    union { uint4 u; __half2 h[4]; } c; c.u = s;
    addf32x2(acc[0], __half22float2(c.h[0]));
    addf32x2(acc[1], __half22float2(c.h[1]));
    addf32x2(acc[2], __half22float2(c.h[2]));
    addf32x2(acc[3], __half22float2(c.h[3]));
}

// ---------------------------------------------------------------------------
// Kernel 2: ONE warp per segment; gathers land in SMEM via cp.async (LDGSTS)
// so in-flight bytes are not register-file-bound. Per warp: 2-group ring of
// 4-token slots (4KB), issue-ahead 8 tokens, wait_prior(1); empty commits at
// the tail keep group accounting aligned. Consumer: LDS.128 + HADD2 into 2
// rotating fp16 sets, flushed to packed f32x2 every 16 tokens.
// ---------------------------------------------------------------------------
__global__ void __launch_bounds__(256)
seg_sum_kernel(const int* __restrict__ token_ids,
               float4*    __restrict__ out)        // [2][NSEG][32] float4
{
    __shared__ uint4 slots[8][2][4][32];           // 32KB: warp/group/token/lane

    const int w    = threadIdx.x >> 5;
    const int lane = threadIdx.x & 31;
    const int seg  = blockIdx.x * 8 + w;           // grid = NSEG/8

    const int beg = g_seg_start[seg];
    const int end = g_seg_start[seg + 1];
    const int cnt = end - beg;
    const int lim = (cnt + 3) & ~3;                // padded (token 0 = zero row)

    // Token-id window: cur = chunk cc, nxt = chunk cc+1 (32 tokens each).
    int cc = 0;
    auto fetchids = [&](int c) -> int {
        int pos = beg + (c << 5) + lane;
        return (pos < end) ? __ldg(&token_ids[pos]) : 0;
    };
    int cur = fetchids(0);
    int nxt = fetchids(1);

    // Issue 4 tokens starting at (monotonically increasing) pos into the
    // ring slot (pos>>2)&1, then commit the group.
    auto issue4 = [&](int pos) {
        if ((pos >> 5) != cc) {                    // crossed into next chunk
            cc = pos >> 5;
            cur = nxt;
            nxt = fetchids(cc + 1);
        }
        const int q = pos & 31;
        const int s = (pos >> 2) & 1;
        int t0 = __shfl_sync(0xffffffffu, cur, q + 0);
        int t1 = __shfl_sync(0xffffffffu, cur, q + 1);
        int t2 = __shfl_sync(0xffffffffu, cur, q + 2);
        int t3 = __shfl_sync(0xffffffffu, cur, q + 3);
        __pipeline_memcpy_async(&slots[w][s][0][lane], &g_pack[t0 * 32 + lane], 16);
        __pipeline_memcpy_async(&slots[w][s][1][lane], &g_pack[t1 * 32 + lane], 16);
        __pipeline_memcpy_async(&slots[w][s][2][lane], &g_pack[t2 * 32 + lane], 16);
        __pipeline_memcpy_async(&slots[w][s][3][lane], &g_pack[t3 * 32 + lane], 16);
        __pipeline_commit();
    };

    // Prologue: always commit exactly 2 groups (empty if out of range).
    if (lim > 0) issue4(0); else __pipeline_commit();
    if (lim > 4) issue4(4); else __pipeline_commit();

    unsigned long long acc[4] = {0ull, 0ull, 0ull, 0ull};
    const uint4 z4 = make_uint4(0u, 0u, 0u, 0u);
    uint4 h0 = z4, h1 = z4;

    for (int u = 0; u < lim; u += 4) {
        __pipeline_wait_prior(1);                  // group at u is complete
        const int s = (u >> 2) & 1;
        uint4 r0 = slots[w][s][0][lane];
        uint4 r1 = slots[w][s][1][lane];
        uint4 r2 = slots[w][s][2][lane];
        uint4 r3 = slots[w][s][3][lane];
        // Refill this slot for u+8 (LDS above issued first; cp.async data
        // cannot land before L2 latency >> LDS latency).
        if (u + 8 < lim) issue4(u + 8); else __pipeline_commit();

        h0 = hadd2x4(h0, r0);
        h1 = hadd2x4(h1, r1);
        h0 = hadd2x4(h0, r2);
        h1 = hadd2x4(h1, r3);
        if ((u & 12) == 12) {                      // flush every 16 tokens
            flush_set(acc, h0); flush_set(acc, h1);
            h0 = z4; h1 = z4;
        }
    }
    flush_set(acc, h0);
    flush_set(acc, h1);

    float2 f0 = u64_to_f2(acc[0]);
    float2 f1 = u64_to_f2(acc[1]);
    float2 f2 = u64_to_f2(acc[2]);
    float2 f3 = u64_to_f2(acc[3]);

    // lanes 0-15: key row floats [8*lane, 8*lane+8); lanes 16-31: value row.
    const int tbl = lane >> 4;
    const int col = lane & 15;
    float4* dst = &out[(((size_t)tbl * NSEG) + seg) * 32 + col * 2];
    dst[0] = make_float4(f0.x, f0.y, f1.x, f1.y);
    dst[1] = make_float4(f2.x, f2.y, f3.x, f3.y);
}

// ---------------------------------------------------------------------------
// Launch
// ---------------------------------------------------------------------------
extern "C" void kernel_launch(void* const* d_in, const int* in_sizes, int n_in,
                              void* d_out, int out_size) {
    const int*    token_ids = (const int*)   d_in[0];
    const int*    tree_ids  = (const int*)   d_in[1];
    const float4* C_hop     = (const float4*)d_in[2];
    const float4* C_hop1    = (const float4*)d_in[3];
    float4*       out       = (float4*)      d_out;

    const int n = in_sizes[0];  // TOTAL_TOKENS

    // Kernel 0: fused table conversion + segment bounds
    prep_kernel<<<CONV_BLOCKS + BOUND_BLOCKS, 256>>>(C_hop, C_hop1, tree_ids, n);

    // Kernel 2: 1 warp/segment, 8 segments/block -> 2048 blocks
    seg_sum_kernel<<<NSEG / 8, 256>>>(token_ids, out);
}

// round 15
// speedup vs baseline: 1.1043x; 1.0129x over previous
#include <cuda_runtime.h>
#include <cuda_fp16.h>
#include <cuda_pipeline.h>

// Problem constants (fixed by reference)
#define VOCAB      32000
#define EMBED_DIM  128
#define BATCH      32
#define MAX_TREES  512
#define NSEG       (BATCH * MAX_TREES)   // 16384

#define CONV_BLOCKS   4000               // blocks doing table conversion
#define BOUND_BLOCKS  65                 // blocks doing segment bounds

// Scratch (allocation-free __device__ globals)
__device__ int g_seg_start[NSEG + 1];
// Packed interleaved fp16 tables: per token, 512B record =
//   [128 fp16 key row | 128 fp16 value row] = 32 uint4 (lane l owns uint4 l).
// Row 0 (PAD token) is exactly zero -> safe padding target.
__device__ __align__(16) uint4 g_pack[VOCAB * 32];

// ---------------------------------------------------------------------------
// Kernel 0 (fused): blocks [0, CONV_BLOCKS) convert the f32 tables to packed
// fp16; remaining blocks binary-search segment boundaries.
// ---------------------------------------------------------------------------
__global__ void __launch_bounds__(256)
prep_kernel(const float4* __restrict__ C_hop,
            const float4* __restrict__ C_hop1,
            const int*    __restrict__ tree_ids, int n) {
    if (blockIdx.x < CONV_BLOCKS) {
        const int NT = VOCAB * 32;                 // 1,024,000 output uint4s
        int j = blockIdx.x * blockDim.x + threadIdx.x;
        if (j >= NT) return;
        const int r = j >> 5;                      // token row
        const int c = j & 31;                      // uint4 slot in 512B record
        const float4* src = (c < 16) ? C_hop : C_hop1;
        const int cc = c & 15;

        float4 a0 = __ldg(&src[r * 32 + 2 * cc]);
        float4 a1 = __ldg(&src[r * 32 + 2 * cc + 1]);

        union { __half2 h2[4]; uint4 u; } p;
        p.h2[0] = __floats2half2_rn(a0.x, a0.y);
        p.h2[1] = __floats2half2_rn(a0.z, a0.w);
        p.h2[2] = __floats2half2_rn(a1.x, a1.y);
        p.h2[3] = __floats2half2_rn(a1.z, a1.w);
        g_pack[j] = p.u;
    } else {
        int s = (blockIdx.x - CONV_BLOCKS) * blockDim.x + threadIdx.x;
        if (s > NSEG) return;
        int lo = 0, hi = n;
        while (lo < hi) {
            int mid = (lo + hi) >> 1;
            if (__ldg(&tree_ids[mid]) < s) lo = mid + 1;
            else hi = mid;
        }
        g_seg_start[s] = lo;
    }
}

// ---------------------------------------------------------------------------
// Helpers: packed f32x2 accumulate (Blackwell add.rn.f32x2) + fp16x8 adds
// ---------------------------------------------------------------------------
__device__ __forceinline__ void addf32x2(unsigned long long& a, float2 f) {
    unsigned long long b;
    asm("mov.b64 %0, {%1, %2};" : "=l"(b) : "f"(f.x), "f"(f.y));
    asm("add.rn.f32x2 %0, %0, %1;" : "+l"(a) : "l"(b));
}
__device__ __forceinline__ float2 u64_to_f2(unsigned long long a) {
    float2 f;
    asm("mov.b64 {%0, %1}, %2;" : "=f"(f.x), "=f"(f.y) : "l"(a));
    return f;
}
__device__ __forceinline__ uint4 hadd2x4(uint4 a, uint4 b) {
    union U { uint4 u; __half2 h[4]; };
    U x, y, r; x.u = a; y.u = b;
    r.h[0] = __hadd2(x.h[0], y.h[0]);
    r.h[1] = __hadd2(x.h[1], y.h[1]);
    r.h[2] = __hadd2(x.h[2], y.h[2]);
    r.h[3] = __hadd2(x.h[3], y.h[3]);
    return r.u;
}
__device__ __forceinline__ void flush_set(unsigned long long acc[4], uint4 s) {
    union { uint4 u; __half2 h[4]; } c; c.u = s;
    addf32x2(acc[0], __half22float2(c.h[0]));
    addf32x2(acc[1], __half22float2(c.h[1]));
    addf32x2(acc[2], __half22float2(c.h[2]));
    addf32x2(acc[3], __half22float2(c.h[3]));
}

// ---------------------------------------------------------------------------
// Kernel 2: ONE warp per segment; gathers land in SMEM via cp.async so
// in-flight bytes are smem-bound, not register-bound. Per warp: 4-group ring
// of 4-token slots (8KB), issue-ahead 16 tokens, wait_prior(3); empty
// commits keep group accounting aligned at the tail. 4 warps/block (32KB) ->
// ~7 blocks/SM -> ~224KB of gathers in flight per SM. Consumer: LDS.128 +
// HADD2 into 2 rotating fp16 sets, flushed to packed f32x2 every 16 tokens.
// ---------------------------------------------------------------------------
__global__ void __launch_bounds__(128)
seg_sum_kernel(const int* __restrict__ token_ids,
               float4*    __restrict__ out)        // [2][NSEG][32] float4
{
    __shared__ uint4 slots[4][4][4][32];           // 32KB: warp/group/token/lane

    const int w    = threadIdx.x >> 5;
    const int lane = threadIdx.x & 31;
    const int seg  = blockIdx.x * 4 + w;           // grid = NSEG/4

    const int beg = g_seg_start[seg];
    const int end = g_seg_start[seg + 1];
    const int cnt = end - beg;
    const int lim = (cnt + 3) & ~3;                // padded (token 0 = zero row)

    // Token-id window: cur = chunk cc, nxt = chunk cc+1 (32 tokens each).
    int cc = 0;
    auto fetchids = [&](int c) -> int {
        int pos = beg + (c << 5) + lane;
        return (pos < end) ? __ldg(&token_ids[pos]) : 0;
    };
    int cur = fetchids(0);
    int nxt = fetchids(1);

    // Issue 4 tokens starting at (monotonically increasing) pos into ring
    // slot (pos>>2)&3, then commit the group.
    auto issue4 = [&](int pos) {
        if ((pos >> 5) != cc) {                    // crossed into next chunk
            cc = pos >> 5;
            cur = nxt;
            nxt = fetchids(cc + 1);
        }
        const int q = pos & 31;
        const int s = (pos >> 2) & 3;
        int t0 = __shfl_sync(0xffffffffu, cur, q + 0);
        int t1 = __shfl_sync(0xffffffffu, cur, q + 1);
        int t2 = __shfl_sync(0xffffffffu, cur, q + 2);
        int t3 = __shfl_sync(0xffffffffu, cur, q + 3);
        __pipeline_memcpy_async(&slots[w][s][0][lane], &g_pack[t0 * 32 + lane], 16);
        __pipeline_memcpy_async(&slots[w][s][1][lane], &g_pack[t1 * 32 + lane], 16);
        __pipeline_memcpy_async(&slots[w][s][2][lane], &g_pack[t2 * 32 + lane], 16);
        __pipeline_memcpy_async(&slots[w][s][3][lane], &g_pack[t3 * 32 + lane], 16);
        __pipeline_commit();
    };

    // Prologue: always commit exactly 4 groups (empty if out of range).
    #pragma unroll
    for (int p = 0; p < 4; p++) {
        if (p * 4 < lim) issue4(p * 4); else __pipeline_commit();
    }

    unsigned long long acc[4] = {0ull, 0ull, 0ull, 0ull};
    const uint4 z4 = make_uint4(0u, 0u, 0u, 0u);
    uint4 h0 = z4, h1 = z4;

    for (int u = 0; u < lim; u += 4) {
        __pipeline_wait_prior(3);                  // group at u is complete
        const int s = (u >> 2) & 3;
        uint4 r0 = slots[w][s][0][lane];
        uint4 r1 = slots[w][s][1][lane];
        uint4 r2 = slots[w][s][2][lane];
        uint4 r3 = slots[w][s][3][lane];
        // Refill this slot for u+16 (reads above complete before cp.async
        // data could land: L2 latency >> LDS latency).
        if (u + 16 < lim) issue4(u + 16); else __pipeline_commit();

        h0 = hadd2x4(h0, r0);
        h1 = hadd2x4(h1, r1);
        h0 = hadd2x4(h0, r2);
        h1 = hadd2x4(h1, r3);
        if ((u & 12) == 12) {                      // flush every 16 tokens
            flush_set(acc, h0); flush_set(acc, h1);
            h0 = z4; h1 = z4;
        }
    }
    flush_set(acc, h0);
    flush_set(acc, h1);

    float2 f0 = u64_to_f2(acc[0]);
    float2 f1 = u64_to_f2(acc[1]);
    float2 f2 = u64_to_f2(acc[2]);
    float2 f3 = u64_to_f2(acc[3]);

    // lanes 0-15: key row floats [8*lane, 8*lane+8); lanes 16-31: value row.
    const int tbl = lane >> 4;
    const int col = lane & 15;
    float4* dst = &out[(((size_t)tbl * NSEG) + seg) * 32 + col * 2];
    dst[0] = make_float4(f0.x, f0.y, f1.x, f1.y);
    dst[1] = make_float4(f2.x, f2.y, f3.x, f3.y);
}

// ---------------------------------------------------------------------------
// Launch
// ---------------------------------------------------------------------------
extern "C" void kernel_launch(void* const* d_in, const int* in_sizes, int n_in,
                              void* d_out, int out_size) {
    const int*    token_ids = (const int*)   d_in[0];
    const int*    tree_ids  = (const int*)   d_in[1];
    const float4* C_hop     = (const float4*)d_in[2];
    const float4* C_hop1    = (const float4*)d_in[3];
    float4*       out       = (float4*)      d_out;

    const int n = in_sizes[0];  // TOTAL_TOKENS

    // Kernel 0: fused table conversion + segment bounds
    prep_kernel<<<CONV_BLOCKS + BOUND_BLOCKS, 256>>>(C_hop, C_hop1, tree_ids, n);

    // Kernel 2: 1 warp/segment, 4 segments/block -> 4096 blocks
    seg_sum_kernel<<<NSEG / 4, 128>>>(token_ids, out);
}